// round 14
// baseline (speedup 1.0000x reference)
#include <cuda_runtime.h>
#include <cuda_fp16.h>
#include <mma.h>
#include <cstdint>

using namespace nvcuda;

__device__ __forceinline__ float2 cmul(float2 a, float2 b) {
    return make_float2(fmaf(a.x, b.x, -a.y * b.y), fmaf(a.x, b.y, a.y * b.x));
}

// Cody-Waite reduction to ~[-pi, pi]; exact for |ph| <~ 25000
__device__ __forceinline__ float red2pi(float ph) {
    float q = rintf(ph * 0.15915494309f);
    ph = fmaf(q, -6.28125f, ph);
    ph = fmaf(q, -1.93530717e-3f, ph);
    return ph;
}

// ============================ WMMA kernel (transposed, split-barrier) ============
// One CTA (128 thr, 4 warps) per head h.  l = 64j + i, j in [0,32), i in [0,64).
//   out[h, 64j+i] = sum_n [ ReW^j * 2ReP  -  ImW^j * 2ImP ],  P = Cd*E^i, W = E^64.
// GEMM D[j][i] = A'[32j x 64k] * B'[64k x 64i], k-interleaved (k=2n Re, 2n+1 Im):
//   A'[j][2n] = Re W^j,  A'[j][2n+1] = Im W^j          (row-major)
//   B'[2n][i] = 2 Re P,  B'[2n+1][i] = -2 Im P         (stored col-major)
// B' = conj(2Cd * E^i) via conjugated constants. D row-major in gmem (ld=64).
// Single-pass fp16 (measured rel_err 2.286e-4).
// ORDERING: A' (cross-warp shared, small) is generated BEFORE the one
// __syncthreads; B' (large, strictly warp-local: warp w writes cols
// 16w..16w+15 and is the only consumer) moves AFTER it, needing only a
// __syncwarp. This keeps the global barrier off the fat gen block.
// 7 CTAs/SM -> grid 1024 runs in exactly one wave on 148 SMs.

static constexpr int LDA = 72;   // fp16 elems; 144 B rows, 16B-aligned

__global__ __launch_bounds__(128, 7)
void s4d_wmma(const float* __restrict__ log_dt,
              const float* __restrict__ Cr,
              const float* __restrict__ logAre,
              const float* __restrict__ Aimag,
              float* __restrict__ out)
{
    __shared__ __half Asm[32 * LDA];    // W-powers,  4608 B
    __shared__ __half Bsm[64 * LDA];    // P-values,  9216 B  -> 13824 B total

    const int h   = blockIdx.x;
    const int tid = threadIdx.x;
    const int wid = tid >> 5;           // 0..3
    const int n   = tid & 31;           // lane = mode

    // ---- per-lane constants (redundant per warp, all registers) ----
    const float dt  = __expf(log_dt[h]);
    const float Are = -__expf(logAre[h * 32 + n]);
    const float Ai  = Aimag[h * 32 + n];
    const float dre = Are * dt;
    const float dim = Ai * dt;                  // |dim| <= ~9.8

    float sn, cs;
    __sincosf(dim, &sn, &cs);
    const float e1 = __expf(dre);
    const float2 E = make_float2(e1 * cs, e1 * sn);
    const float inv = __frcp_rn(fmaf(Are, Are, Ai * Ai));
    const float ccre = Cr[(h * 32 + n) * 2 + 0];
    const float ccim = Cr[(h * 32 + n) * 2 + 1];
    const float numre = E.x - 1.0f, numim = E.y;
    const float tre = ccre * numre - ccim * numim;
    const float tim = ccre * numim + ccim * numre;
    // conj(2*Cd):
    const float2 Cdc2 = make_float2( 2.0f * (tre * Are + tim * Ai) * inv,
                                    -2.0f * (tim * Are - tre * Ai) * inv);
    // conj(E) and its powers (for B' = conj(2Cd * E^i)):
    const float2 Ec   = make_float2(E.x, -E.y);
    const float2 Ec2  = cmul(Ec, Ec);
    const float2 Ec4  = cmul(Ec2, Ec2);
    const float2 Ec8  = cmul(Ec4, Ec4);
    const float2 Ec16 = cmul(Ec8, Ec8);
    const float2 Ec32 = cmul(Ec16, Ec16);

    // W = exp(64*dtA) direct; powers for A'
    const float ph = red2pi(dim * 64.0f);       // |arg| <= ~630, exact CW range
    float snT, csT;
    __sincosf(ph, &snT, &csT);
    const float eT = __expf(dre * 64.0f);       // >= e^-3.2
    const float2 W   = make_float2(eT * csT, eT * snT);
    const float2 W2  = cmul(W, W);
    const float2 W4  = cmul(W2, W2);
    const float2 W8  = cmul(W4, W4);
    const float2 W16 = cmul(W8, W8);

    // ---- gen A' (shared across warps): rows j = 8*wid .. 8*wid+7 (W^j) ----
    {
        float2 base = make_float2(1.0f, 0.0f);   // W^(8*wid)
        if (wid & 1) base = W8;
        if (wid & 2) base = cmul(base, W16);
        float2 z[8];
        z[0] = base;
        z[1] = cmul(base, W);
        z[2] = cmul(base, W2);
        z[4] = cmul(base, W4);
        z[3] = cmul(z[1], W2);
        z[5] = cmul(z[1], W4);
        z[6] = cmul(z[2], W4);
        z[7] = cmul(z[3], W4);
        #pragma unroll
        for (int s = 0; s < 8; s++) {
            const int j = wid * 8 + s;
            ((__half2*)(Asm + j * LDA))[n] = __floats2half2_rn(z[s].x, z[s].y);
        }
    }
    __syncthreads();   // only A' (small) gated by the global barrier

    // ---- gen B' (warp-local): cols i = 16*wid .. 16*wid+15, conj(2Cd*E^i) ----
    {
        float2 base = Cdc2;                      // conj(2Cd) * Ec^(16*wid)
        if (wid & 1) base = cmul(base, Ec16);
        if (wid & 2) base = cmul(base, Ec32);
        float2 z[16];
        z[0] = base;
        z[1] = cmul(base, Ec);
        z[2] = cmul(base, Ec2);
        z[4] = cmul(base, Ec4);
        z[3] = cmul(z[1], Ec2);
        z[5] = cmul(z[1], Ec4);
        z[6] = cmul(z[2], Ec4);
        z[7] = cmul(z[3], Ec4);
        #pragma unroll
        for (int s = 0; s < 8; s++) z[8 + s] = cmul(z[s], Ec8);
        #pragma unroll
        for (int s = 0; s < 16; s++) {
            const int i = wid * 16 + s;
            ((__half2*)(Bsm + i * LDA))[n] = __floats2half2_rn(z[s].x, z[s].y);
        }
    }
    __syncwarp();      // intra-warp smem ordering for self-consumed B'

    // ---- WMMA: warp wid owns i-tile it=wid; loop jt = 0,1 over j-tiles ----
    {
        const int it = wid;
        wmma::fragment<wmma::matrix_b, 16, 16, 16, __half, wmma::col_major> bf[4];
        #pragma unroll
        for (int kt = 0; kt < 4; kt++)
            wmma::load_matrix_sync(bf[kt], Bsm + (it * 16) * LDA + kt * 16, LDA);

        #pragma unroll
        for (int jt = 0; jt < 2; jt++) {
            wmma::fragment<wmma::matrix_a, 16, 16, 16, __half, wmma::row_major> af;
            wmma::fragment<wmma::accumulator, 16, 16, 16, float> acc;
            wmma::fill_fragment(acc, 0.0f);
            #pragma unroll
            for (int kt = 0; kt < 4; kt++) {
                wmma::load_matrix_sync(af, Asm + (jt * 16) * LDA + kt * 16, LDA);
                wmma::mma_sync(acc, af, bf[kt], acc);
            }
            // D[j][i] -> out[h*2048 + j*64 + i], row-major, ld = 64
            float* op = out + (size_t)h * 2048 + (size_t)(jt * 16) * 64 + it * 16;
            wmma::store_matrix_sync(op, acc, 64, wmma::mem_row_major);
        }
    }
}

// ---------------- generic fallback (any H, N2, L) ----------------
__global__ void s4d_fallback(
    const float* __restrict__ log_dt,
    const float* __restrict__ Cr,
    const float* __restrict__ logAre,
    const float* __restrict__ Aimag,
    float* __restrict__ out, int H, int N2, int L)
{
    const long long idx = (long long)blockIdx.x * blockDim.x + threadIdx.x;
    if (idx >= (long long)H * L) return;
    const int h = (int)(idx / L);
    const int l = (int)(idx % L);
    const float dt = __expf(log_dt[h]);
    const float lf = (float)l;
    float acc = 0.0f;
    for (int n = 0; n < N2; n++) {
        const float Are = -__expf(logAre[h * N2 + n]);
        const float Ai  = Aimag[h * N2 + n];
        const float dre = Are * dt;
        const float dim = Ai * dt;
        float s1, c1;
        __sincosf(dim, &s1, &c1);
        const float e1 = __expf(dre);
        const float numre = fmaf(e1, c1, -1.0f);
        const float numim = e1 * s1;
        const float inv  = __frcp_rn(fmaf(Are, Are, Ai * Ai));
        const float ccre = Cr[(h * N2 + n) * 2 + 0];
        const float ccim = Cr[(h * N2 + n) * 2 + 1];
        const float tre = ccre * numre - ccim * numim;
        const float tim = ccre * numim + ccim * numre;
        const float cdre = (tre * Are + tim * Ai) * inv;
        const float cdim = (tim * Are - tre * Ai) * inv;
        const float ph = red2pi(dim * lf);
        float s, c;
        __sincosf(ph, &s, &c);
        const float r = __expf(dre * lf);
        acc += r * (cdre * c - cdim * s);
    }
    out[idx] = 2.0f * acc;
}

extern "C" void kernel_launch(void* const* d_in, const int* in_sizes, int n_in,
                              void* d_out, int out_size)
{
    const float* log_dt = (const float*)d_in[0];
    const float* Cr     = (const float*)d_in[1];
    const float* lar    = (const float*)d_in[2];
    const float* aim    = (const float*)d_in[3];
    float* out = (float*)d_out;

    const int H  = in_sizes[0];
    const int N2 = (H > 0) ? in_sizes[2] / H : 0;
    const int L  = (H > 0) ? out_size / H : 0;

    if (N2 == 32 && L == 2048) {
        s4d_wmma<<<H, 128>>>(log_dt, Cr, lar, aim, out);
    } else {
        const long long total = (long long)H * L;
        const int blocks = (int)((total + 127) / 128);
        s4d_fallback<<<blocks, 128>>>(log_dt, Cr, lar, aim, out, H, N2, L);
    }
}

// round 15
// speedup vs baseline: 1.0234x; 1.0234x over previous
#include <cuda_runtime.h>
#include <cuda_fp16.h>
#include <mma.h>
#include <cstdint>

using namespace nvcuda;

__device__ __forceinline__ float2 cmul(float2 a, float2 b) {
    return make_float2(fmaf(a.x, b.x, -a.y * b.y), fmaf(a.x, b.y, a.y * b.x));
}

// Cody-Waite reduction to ~[-pi, pi]; exact for |ph| <~ 25000
__device__ __forceinline__ float red2pi(float ph) {
    float q = rintf(ph * 0.15915494309f);
    ph = fmaf(q, -6.28125f, ph);
    ph = fmaf(q, -1.93530717e-3f, ph);
    return ph;
}

// ===================== two-head WMMA kernel (transposed GEMM) =====================
// Grid = H/2, CTA = 128 thr (4 warps). CTA b computes heads 2b and 2b+1.
//   out[h, 64j+i] = sum_n 2*Re(Cd * E^i * W^j),  E = exp(dtA), W = E^64.
// Per head: GEMM D[j][i] = A'[32j x 64k] * B'[64k x 64i], k-interleaved
// (k=2n Re, k=2n+1 Im); B' = conj(2Cd * E^i) (conjugated constants fold the
// sign), A' = W^j. D row-major in gmem (ld=64). Single-pass fp16
// (measured rel_err 2.286e-4).
// The two heads share one LDG burst, one __syncthreads, and interleave their
// independent MUFU/FFMA/MMA chains in the warp scheduler -- head1's gen fills
// head0's memory/MMA stalls. B' stays warp-local (syncwarp only).

static constexpr int LDA = 72;   // fp16 elems; 144 B rows, 16B-aligned

struct MC {
    float2 Cdc2, Ec, Ec2, Ec4, Ec8, Ec16, Ec32;   // for B' = conj(2Cd*E^i)
    float2 W, W2, W4, W8, W16;                    // for A' = W^j
};

__device__ __forceinline__ MC make_consts(float ldt, float lar, float Ai,
                                          float ccre, float ccim) {
    MC m;
    const float dt  = __expf(ldt);
    const float Are = -__expf(lar);
    const float dre = Are * dt;
    const float dim = Ai * dt;                    // |dim| <= ~9.8
    float sn, cs;
    __sincosf(dim, &sn, &cs);
    const float e1 = __expf(dre);
    const float2 E = make_float2(e1 * cs, e1 * sn);
    const float inv = __frcp_rn(fmaf(Are, Are, Ai * Ai));
    const float numre = E.x - 1.0f, numim = E.y;
    const float tre = ccre * numre - ccim * numim;
    const float tim = ccre * numim + ccim * numre;
    m.Cdc2 = make_float2( 2.0f * (tre * Are + tim * Ai) * inv,
                         -2.0f * (tim * Are - tre * Ai) * inv);
    m.Ec   = make_float2(E.x, -E.y);
    m.Ec2  = cmul(m.Ec,  m.Ec);
    m.Ec4  = cmul(m.Ec2, m.Ec2);
    m.Ec8  = cmul(m.Ec4, m.Ec4);
    m.Ec16 = cmul(m.Ec8, m.Ec8);
    m.Ec32 = cmul(m.Ec16, m.Ec16);
    const float ph = red2pi(dim * 64.0f);         // |arg| <= ~630, exact CW
    float snT, csT;
    __sincosf(ph, &snT, &csT);
    const float eT = __expf(dre * 64.0f);         // >= e^-3.2
    m.W   = make_float2(eT * csT, eT * snT);
    m.W2  = cmul(m.W,  m.W);
    m.W4  = cmul(m.W2, m.W2);
    m.W8  = cmul(m.W4, m.W4);
    m.W16 = cmul(m.W8, m.W8);
    return m;
}

// A' rows j = 8*wid .. 8*wid+7  (W^j), shared across warps
__device__ __forceinline__ void gen_A(const MC& m, __half* Asm, int wid, int n) {
    float2 base = make_float2(1.0f, 0.0f);
    if (wid & 1) base = m.W8;
    if (wid & 2) base = cmul(base, m.W16);
    float2 z[8];
    z[0] = base;
    z[1] = cmul(base, m.W);
    z[2] = cmul(base, m.W2);
    z[4] = cmul(base, m.W4);
    z[3] = cmul(z[1], m.W2);
    z[5] = cmul(z[1], m.W4);
    z[6] = cmul(z[2], m.W4);
    z[7] = cmul(z[3], m.W4);
    #pragma unroll
    for (int s = 0; s < 8; s++)
        ((__half2*)(Asm + (wid * 8 + s) * LDA))[n] = __floats2half2_rn(z[s].x, z[s].y);
}

// B' cols i = 16*wid .. 16*wid+15  (conj(2Cd*E^i)), strictly warp-local
__device__ __forceinline__ void gen_B(const MC& m, __half* Bsm, int wid, int n) {
    float2 base = m.Cdc2;
    if (wid & 1) base = cmul(base, m.Ec16);
    if (wid & 2) base = cmul(base, m.Ec32);
    float2 z[16];
    z[0] = base;
    z[1] = cmul(base, m.Ec);
    z[2] = cmul(base, m.Ec2);
    z[4] = cmul(base, m.Ec4);
    z[3] = cmul(z[1], m.Ec2);
    z[5] = cmul(z[1], m.Ec4);
    z[6] = cmul(z[2], m.Ec4);
    z[7] = cmul(z[3], m.Ec4);
    #pragma unroll
    for (int s = 0; s < 8; s++) z[8 + s] = cmul(z[s], m.Ec8);
    #pragma unroll
    for (int s = 0; s < 16; s++)
        ((__half2*)(Bsm + (wid * 16 + s) * LDA))[n] = __floats2half2_rn(z[s].x, z[s].y);
}

// Warp wid owns i-tile it=wid; jt = 0,1. D[j][i] -> outh[j*64 + i], row-major.
__device__ __forceinline__ void mma_store(const __half* Asm, const __half* Bsm,
                                          float* outh, int wid) {
    const int it = wid;
    wmma::fragment<wmma::matrix_b, 16, 16, 16, __half, wmma::col_major> bf[4];
    #pragma unroll
    for (int kt = 0; kt < 4; kt++)
        wmma::load_matrix_sync(bf[kt], Bsm + (it * 16) * LDA + kt * 16, LDA);
    #pragma unroll
    for (int jt = 0; jt < 2; jt++) {
        wmma::fragment<wmma::matrix_a, 16, 16, 16, __half, wmma::row_major> af;
        wmma::fragment<wmma::accumulator, 16, 16, 16, float> acc;
        wmma::fill_fragment(acc, 0.0f);
        #pragma unroll
        for (int kt = 0; kt < 4; kt++) {
            wmma::load_matrix_sync(af, Asm + (jt * 16) * LDA + kt * 16, LDA);
            wmma::mma_sync(acc, af, bf[kt], acc);
        }
        wmma::store_matrix_sync(outh + (size_t)(jt * 16) * 64 + it * 16,
                                acc, 64, wmma::mem_row_major);
    }
}

__global__ __launch_bounds__(128, 4)
void s4d_wmma2(const float* __restrict__ log_dt,
               const float* __restrict__ Cr,
               const float* __restrict__ logAre,
               const float* __restrict__ Aimag,
               float* __restrict__ out)
{
    __shared__ __half Asm[2][32 * LDA];   // 2 x 4608 B
    __shared__ __half Bsm[2][64 * LDA];   // 2 x 9216 B  -> 27648 B total

    const int h0  = blockIdx.x * 2;
    const int h1  = h0 + 1;
    const int tid = threadIdx.x;
    const int wid = tid >> 5;
    const int n   = tid & 31;

    // one LDG burst for both heads (8 loads in flight)
    const float  ldt0 = log_dt[h0],            ldt1 = log_dt[h1];
    const float  lar0 = logAre[h0 * 32 + n],   lar1 = logAre[h1 * 32 + n];
    const float  ai0  = Aimag[h0 * 32 + n],    ai1  = Aimag[h1 * 32 + n];
    const float2 cc0  = ((const float2*)Cr)[h0 * 32 + n];
    const float2 cc1  = ((const float2*)Cr)[h1 * 32 + n];

    const MC m0 = make_consts(ldt0, lar0, ai0, cc0.x, cc0.y);
    const MC m1 = make_consts(ldt1, lar1, ai1, cc1.x, cc1.y);

    gen_A(m0, Asm[0], wid, n);
    gen_A(m1, Asm[1], wid, n);
    __syncthreads();                       // single global barrier (A' only)

    gen_B(m0, Bsm[0], wid, n);
    __syncwarp();
    mma_store(Asm[0], Bsm[0], out + (size_t)h0 * 2048, wid);

    gen_B(m1, Bsm[1], wid, n);             // issues under head0's MMA/STG latency
    __syncwarp();
    mma_store(Asm[1], Bsm[1], out + (size_t)h1 * 2048, wid);
}

// ---------------- generic fallback (any H, N2, L) ----------------
__global__ void s4d_fallback(
    const float* __restrict__ log_dt,
    const float* __restrict__ Cr,
    const float* __restrict__ logAre,
    const float* __restrict__ Aimag,
    float* __restrict__ out, int H, int N2, int L)
{
    const long long idx = (long long)blockIdx.x * blockDim.x + threadIdx.x;
    if (idx >= (long long)H * L) return;
    const int h = (int)(idx / L);
    const int l = (int)(idx % L);
    const float dt = __expf(log_dt[h]);
    const float lf = (float)l;
    float acc = 0.0f;
    for (int n = 0; n < N2; n++) {
        const float Are = -__expf(logAre[h * N2 + n]);
        const float Ai  = Aimag[h * N2 + n];
        const float dre = Are * dt;
        const float dim = Ai * dt;
        float s1, c1;
        __sincosf(dim, &s1, &c1);
        const float e1 = __expf(dre);
        const float numre = fmaf(e1, c1, -1.0f);
        const float numim = e1 * s1;
        const float inv  = __frcp_rn(fmaf(Are, Are, Ai * Ai));
        const float ccre = Cr[(h * N2 + n) * 2 + 0];
        const float ccim = Cr[(h * N2 + n) * 2 + 1];
        const float tre = ccre * numre - ccim * numim;
        const float tim = ccre * numim + ccim * numre;
        const float cdre = (tre * Are + tim * Ai) * inv;
        const float cdim = (tim * Are - tre * Ai) * inv;
        const float ph = red2pi(dim * lf);
        float s, c;
        __sincosf(ph, &s, &c);
        const float r = __expf(dre * lf);
        acc += r * (cdre * c - cdim * s);
    }
    out[idx] = 2.0f * acc;
}

extern "C" void kernel_launch(void* const* d_in, const int* in_sizes, int n_in,
                              void* d_out, int out_size)
{
    const float* log_dt = (const float*)d_in[0];
    const float* Cr     = (const float*)d_in[1];
    const float* lar    = (const float*)d_in[2];
    const float* aim    = (const float*)d_in[3];
    float* out = (float*)d_out;

    const int H  = in_sizes[0];
    const int N2 = (H > 0) ? in_sizes[2] / H : 0;
    const int L  = (H > 0) ? out_size / H : 0;

    if (N2 == 32 && L == 2048 && (H % 2) == 0) {
        s4d_wmma2<<<H / 2, 128>>>(log_dt, Cr, lar, aim, out);
    } else {
        const long long total = (long long)H * L;
        const int blocks = (int)((total + 127) / 128);
        s4d_fallback<<<blocks, 128>>>(log_dt, Cr, lar, aim, out, H, N2, L);
    }
}